// round 1
// baseline (speedup 1.0000x reference)
#include <cuda_runtime.h>
#include <cuda_bf16.h>

// ---------------------------------------------------------------------------
// Problem constants
// ---------------------------------------------------------------------------
#define BB   8
#define PP   8192
#define CC   64
#define MM   2048          // P/4 centers
#define KNbr 32            // NSAMPLE
#define LL   (MM*KNbr)     // 65536 rows per batch
#define RR   (BB*LL)       // 524288 total rows
#define NCH3 128
#define BN_EPS 1e-5f

// ---------------------------------------------------------------------------
// Device scratch (static __device__ arrays: allocation-free)
// ---------------------------------------------------------------------------
__device__ float g_fT [BB*PP*CC];       // feats transposed (B,P,C)   16 MB
__device__ int   g_idx[RR];             // knn indices                 2 MB
__device__ float g_y1 [RR*64];          // layer1 pre-BN             134 MB
__device__ float g_y2 [RR*64];          // layer2 pre-BN             134 MB
__device__ float g_y3 [RR*128];         // layer3 pre-BN             268 MB

__device__ float g_s1[64],  g_q1[64],  g_a1[64],  g_c1[64];
__device__ float g_s2[64],  g_q2[64],  g_a2[64],  g_c2[64];
__device__ float g_s3[128], g_q3[128], g_a3[128], g_c3[128];

static __device__ __forceinline__ unsigned long long umin64(unsigned long long a,
                                                            unsigned long long b) {
    return a < b ? a : b;
}

// ---------------------------------------------------------------------------
// 0) zero the BN stat accumulators (graph replays need fresh state)
// ---------------------------------------------------------------------------
__global__ void init_stats_kernel() {
    int i = threadIdx.x;
    if (i < 64)  { g_s1[i] = 0.f; g_q1[i] = 0.f; g_s2[i] = 0.f; g_q2[i] = 0.f; }
    if (i < 128) { g_s3[i] = 0.f; g_q3[i] = 0.f; }
}

// ---------------------------------------------------------------------------
// 1) transpose feats (B,C,P) -> (B,P,C)
// ---------------------------------------------------------------------------
__global__ void transpose_kernel(const float* __restrict__ feats) {
    __shared__ float tile[32][33];
    int b  = blockIdx.z;
    int c0 = blockIdx.y * 32;
    int p0 = blockIdx.x * 32;
    int tx = threadIdx.x, ty = threadIdx.y;
    const float* src = feats + (b*CC + c0)*PP + p0;
#pragma unroll
    for (int i = 0; i < 32; i += 8)
        tile[ty+i][tx] = src[(ty+i)*PP + tx];
    __syncthreads();
    float* dst = g_fT + (b*PP + p0)*CC + c0;
#pragma unroll
    for (int i = 0; i < 32; i += 8)
        dst[(ty+i)*CC + tx] = tile[tx][ty+i];
}

// ---------------------------------------------------------------------------
// 2) centers + exact 32-NN.  2 centers per block, 256 threads.
//    Selection: iterative extract-min with per-thread cached local minimum.
//    Key = (dist_bits << 32) | idx  -> min gives smallest dist, lowest idx tie.
// ---------------------------------------------------------------------------
__global__ void knn_kernel(const float* __restrict__ xyz,
                           float* __restrict__ out_centers) {
    extern __shared__ float dsm[];                    // 2*8192 floats = 64 KB
    __shared__ unsigned long long red[2][4];
    int tid  = threadIdx.x;
    int pair = blockIdx.x;
    int b    = pair >> 10;                 // / (MM/2)
    int m0   = (pair & 1023) << 1;
    const float* xb = xyz + b*PP*3;

    int pc0 = (int)((float)m0       * (8191.0f/2047.0f));
    int pc1 = (int)((float)(m0 + 1) * (8191.0f/2047.0f));
    float c0x = xb[pc0*3+0], c0y = xb[pc0*3+1], c0z = xb[pc0*3+2];
    float c1x = xb[pc1*3+0], c1y = xb[pc1*3+1], c1z = xb[pc1*3+2];

    float* dist0 = dsm;
    float* dist1 = dsm + PP;

    for (int p = tid; p < PP; p += 256) {
        float x = xb[p*3+0], y = xb[p*3+1], z = xb[p*3+2];
        float dx = x-c0x, dy = y-c0y, dz = z-c0z;
        dist0[p] = dx*dx + dy*dy + dz*dz;
        dx = x-c1x; dy = y-c1y; dz = z-c1z;
        dist1[p] = dx*dx + dy*dy + dz*dz;
    }
    if (tid < 3)       out_centers[(b*MM + m0  )*3 + tid    ] = xb[pc0*3 + tid];
    else if (tid < 6)  out_centers[(b*MM + m0+1)*3 + (tid-3)] = xb[pc1*3 + (tid-3)];
    __syncthreads();

    int half = tid >> 7;
    int ht   = tid & 127;
    float* d = half ? dist1 : dist0;

    unsigned long long best = ~0ull;
#pragma unroll 4
    for (int j = 0; j < 64; j++) {
        int p = ht + (j << 7);
        best = umin64(best, ((unsigned long long)__float_as_uint(d[p]) << 32) | (unsigned)p);
    }

    int* idx_out = g_idx + ((b*MM + m0 + half) << 5);
    for (int r = 0; r < KNbr; r++) {
        unsigned long long v = best;
#pragma unroll
        for (int s = 16; s > 0; s >>= 1)
            v = umin64(v, __shfl_xor_sync(0xffffffffu, v, s));
        if ((tid & 31) == 0) red[half][(tid >> 5) & 3] = v;
        __syncthreads();
        unsigned long long w = umin64(umin64(red[half][0], red[half][1]),
                                      umin64(red[half][2], red[half][3]));
        int widx = (int)(unsigned)(w & 0xffffffffull);
        if (ht == 0) idx_out[r] = widx;
        if ((widx & 127) == ht) {                 // owner invalidates + rescans
            d[widx] = __int_as_float(0x7f800000); // +inf
            best = ~0ull;
#pragma unroll 4
            for (int j = 0; j < 64; j++) {
                int p = ht + (j << 7);
                best = umin64(best, ((unsigned long long)__float_as_uint(d[p]) << 32) | (unsigned)p);
            }
        }
        __syncthreads();
    }
}

// ---------------------------------------------------------------------------
// 3) GEMM1: gather [feats(64) | local_xyz(3)] row, x W1^T + b1 -> y1, stats.
//    Channel order permuted (feats first) for aligned float4; weights permuted
//    identically so the dot product is unchanged.
//    Block: 128 thr, tile 64 rows x 64 cols, thread = 8x4 micro-tile.
// ---------------------------------------------------------------------------
__global__ void gemm1_kernel(const float* __restrict__ xyz,
                             const float* __restrict__ w1,
                             const float* __restrict__ b1) {
    __shared__ float As[64][68];
    __shared__ float Ws[67][64];
    __shared__ float ssum[64], ssq[64];
    int tid = threadIdx.x;
    int rowbase = blockIdx.x * 64;

    for (int t = tid; t < 67*64; t += 128) {
        int k = t >> 6, o = t & 63;
        int ch = (k < 64) ? (k + 3) : (k - 64);   // permuted channel map
        Ws[k][o] = w1[o*67 + ch];
    }
    if (tid < 64) { ssum[tid] = 0.f; ssq[tid] = 0.f; }

    {
        int r = tid >> 1, h = tid & 1;
        int gr = rowbase + r;
        int b  = gr >> 16;
        int m  = (gr >> 5) & (MM - 1);
        int idx = g_idx[gr];
        const float4* frow = (const float4*)(g_fT + ((b << 13) + idx) * 64);
        float4* arow = (float4*)&As[r][0];
#pragma unroll
        for (int q = 0; q < 8; q++) arow[h*8 + q] = frow[h*8 + q];
        if (h == 0) {
            int pc = (int)((float)m * (8191.0f/2047.0f));
            const float* x = xyz + b*PP*3;
            As[r][64] = x[idx*3+0] - x[pc*3+0];
            As[r][65] = x[idx*3+1] - x[pc*3+1];
            As[r][66] = x[idx*3+2] - x[pc*3+2];
        }
    }
    __syncthreads();

    int tx = tid & 15, ty = tid >> 4;
    float acc[8][4];
#pragma unroll
    for (int i = 0; i < 8; i++)
#pragma unroll
        for (int j = 0; j < 4; j++) acc[i][j] = 0.f;

#pragma unroll 4
    for (int k = 0; k < 67; k++) {
        float4 bv = *(const float4*)&Ws[k][tx*4];
#pragma unroll
        for (int i = 0; i < 8; i++) {
            float a = As[ty*8+i][k];
            acc[i][0] = fmaf(a, bv.x, acc[i][0]);
            acc[i][1] = fmaf(a, bv.y, acc[i][1]);
            acc[i][2] = fmaf(a, bv.z, acc[i][2]);
            acc[i][3] = fmaf(a, bv.w, acc[i][3]);
        }
    }

    float bias[4];
#pragma unroll
    for (int j = 0; j < 4; j++) bias[j] = b1[tx*4+j];
    float cs[4] = {0,0,0,0}, cq[4] = {0,0,0,0};
#pragma unroll
    for (int i = 0; i < 8; i++) {
        int gr = rowbase + ty*8 + i;
        float4 o;
        o.x = acc[i][0] + bias[0];
        o.y = acc[i][1] + bias[1];
        o.z = acc[i][2] + bias[2];
        o.w = acc[i][3] + bias[3];
        *(float4*)&g_y1[gr*64 + tx*4] = o;
        cs[0] += o.x; cq[0] += o.x*o.x;
        cs[1] += o.y; cq[1] += o.y*o.y;
        cs[2] += o.z; cq[2] += o.z*o.z;
        cs[3] += o.w; cq[3] += o.w*o.w;
    }
#pragma unroll
    for (int j = 0; j < 4; j++) {
        atomicAdd(&ssum[tx*4+j], cs[j]);
        atomicAdd(&ssq [tx*4+j], cq[j]);
    }
    __syncthreads();
    if (tid < 64) {
        atomicAdd(&g_s1[tid], ssum[tid]);
        atomicAdd(&g_q1[tid], ssq[tid]);
    }
}

// ---------------------------------------------------------------------------
// 4) BN finalize: a = g*rsqrt(var+eps), c = beta - mean*a
// ---------------------------------------------------------------------------
__global__ void finalize_kernel(const float* __restrict__ g,
                                const float* __restrict__ beta, int layer) {
    int i = threadIdx.x;
    float *s, *q, *a, *c; int n;
    if (layer == 1)      { s = g_s1; q = g_q1; a = g_a1; c = g_c1; n = 64;  }
    else if (layer == 2) { s = g_s2; q = g_q2; a = g_a2; c = g_c2; n = 64;  }
    else                 { s = g_s3; q = g_q3; a = g_a3; c = g_c3; n = 128; }
    if (i < n) {
        const float invN = 1.0f / (float)RR;
        float mean = s[i] * invN;
        float var  = fmaxf(q[i] * invN - mean*mean, 0.f);
        float inv  = rsqrtf(var + BN_EPS);
        float aa   = g[i] * inv;
        a[i] = aa;
        c[i] = beta[i] - mean * aa;
    }
}

// ---------------------------------------------------------------------------
// 5) GEMM2: x = relu(a1*y1+c1); y2 = x W2^T + b2; stats.
// ---------------------------------------------------------------------------
__global__ void gemm2_kernel(const float* __restrict__ w2,
                             const float* __restrict__ b2) {
    __shared__ float As[64][68];
    __shared__ float Ws[64][64];
    __shared__ float ssum[64], ssq[64];
    int tid = threadIdx.x;
    int rowbase = blockIdx.x * 64;

    for (int t = tid; t < 64*64; t += 128) {
        int k = t >> 6, o = t & 63;
        Ws[k][o] = w2[o*64 + k];
    }
    if (tid < 64) { ssum[tid] = 0.f; ssq[tid] = 0.f; }

    {
        int r = tid >> 1, h = tid & 1;
        int gr = rowbase + r;
        const float4* yrow = (const float4*)(g_y1 + gr*64);
        float4* arow = (float4*)&As[r][0];
#pragma unroll
        for (int q = 0; q < 8; q++) {
            int f4 = h*8 + q;
            float4 v = yrow[f4];
            int ch = f4*4;
            v.x = fmaxf(fmaf(g_a1[ch+0], v.x, g_c1[ch+0]), 0.f);
            v.y = fmaxf(fmaf(g_a1[ch+1], v.y, g_c1[ch+1]), 0.f);
            v.z = fmaxf(fmaf(g_a1[ch+2], v.z, g_c1[ch+2]), 0.f);
            v.w = fmaxf(fmaf(g_a1[ch+3], v.w, g_c1[ch+3]), 0.f);
            arow[f4] = v;
        }
    }
    __syncthreads();

    int tx = tid & 15, ty = tid >> 4;
    float acc[8][4];
#pragma unroll
    for (int i = 0; i < 8; i++)
#pragma unroll
        for (int j = 0; j < 4; j++) acc[i][j] = 0.f;

#pragma unroll 4
    for (int k = 0; k < 64; k++) {
        float4 bv = *(const float4*)&Ws[k][tx*4];
#pragma unroll
        for (int i = 0; i < 8; i++) {
            float a = As[ty*8+i][k];
            acc[i][0] = fmaf(a, bv.x, acc[i][0]);
            acc[i][1] = fmaf(a, bv.y, acc[i][1]);
            acc[i][2] = fmaf(a, bv.z, acc[i][2]);
            acc[i][3] = fmaf(a, bv.w, acc[i][3]);
        }
    }

    float bias[4];
#pragma unroll
    for (int j = 0; j < 4; j++) bias[j] = b2[tx*4+j];
    float cs[4] = {0,0,0,0}, cq[4] = {0,0,0,0};
#pragma unroll
    for (int i = 0; i < 8; i++) {
        int gr = rowbase + ty*8 + i;
        float4 o;
        o.x = acc[i][0] + bias[0];
        o.y = acc[i][1] + bias[1];
        o.z = acc[i][2] + bias[2];
        o.w = acc[i][3] + bias[3];
        *(float4*)&g_y2[gr*64 + tx*4] = o;
        cs[0] += o.x; cq[0] += o.x*o.x;
        cs[1] += o.y; cq[1] += o.y*o.y;
        cs[2] += o.z; cq[2] += o.z*o.z;
        cs[3] += o.w; cq[3] += o.w*o.w;
    }
#pragma unroll
    for (int j = 0; j < 4; j++) {
        atomicAdd(&ssum[tx*4+j], cs[j]);
        atomicAdd(&ssq [tx*4+j], cq[j]);
    }
    __syncthreads();
    if (tid < 64) {
        atomicAdd(&g_s2[tid], ssum[tid]);
        atomicAdd(&g_q2[tid], ssq[tid]);
    }
}

// ---------------------------------------------------------------------------
// 6) GEMM3: x = relu(a2*y2+c2); y3 = x W3^T + b3 (128 out); stats.
//    Block: 256 thr, tile 32 rows x 128 cols, thread = 4x4 micro-tile.
// ---------------------------------------------------------------------------
__global__ void gemm3_kernel(const float* __restrict__ w3,
                             const float* __restrict__ b3) {
    __shared__ float As[32][68];
    __shared__ float Ws[64][128];
    __shared__ float ssum[128], ssq[128];
    int tid = threadIdx.x;
    int rowbase = blockIdx.x * 32;

    for (int t = tid; t < 64*128; t += 256) {
        int k = t >> 7, o = t & 127;
        Ws[k][o] = w3[o*64 + k];
    }
    if (tid < 128) { ssum[tid] = 0.f; ssq[tid] = 0.f; }

    {
        int r = tid >> 3, q8 = tid & 7;
        int gr = rowbase + r;
        const float4* yrow = (const float4*)(g_y2 + gr*64);
        float4* arow = (float4*)&As[r][0];
#pragma unroll
        for (int u = 0; u < 2; u++) {
            int f4 = q8*2 + u;
            float4 v = yrow[f4];
            int ch = f4*4;
            v.x = fmaxf(fmaf(g_a2[ch+0], v.x, g_c2[ch+0]), 0.f);
            v.y = fmaxf(fmaf(g_a2[ch+1], v.y, g_c2[ch+1]), 0.f);
            v.z = fmaxf(fmaf(g_a2[ch+2], v.z, g_c2[ch+2]), 0.f);
            v.w = fmaxf(fmaf(g_a2[ch+3], v.w, g_c2[ch+3]), 0.f);
            arow[f4] = v;
        }
    }
    __syncthreads();

    int tx = tid & 31, ty = tid >> 5;
    float acc[4][4];
#pragma unroll
    for (int i = 0; i < 4; i++)
#pragma unroll
        for (int j = 0; j < 4; j++) acc[i][j] = 0.f;

#pragma unroll 4
    for (int k = 0; k < 64; k++) {
        float4 bv = *(const float4*)&Ws[k][tx*4];
#pragma unroll
        for (int i = 0; i < 4; i++) {
            float a = As[ty*4+i][k];
            acc[i][0] = fmaf(a, bv.x, acc[i][0]);
            acc[i][1] = fmaf(a, bv.y, acc[i][1]);
            acc[i][2] = fmaf(a, bv.z, acc[i][2]);
            acc[i][3] = fmaf(a, bv.w, acc[i][3]);
        }
    }

    float bias[4];
#pragma unroll
    for (int j = 0; j < 4; j++) bias[j] = b3[tx*4+j];
    float cs[4] = {0,0,0,0}, cq[4] = {0,0,0,0};
#pragma unroll
    for (int i = 0; i < 4; i++) {
        int gr = rowbase + ty*4 + i;
        float4 o;
        o.x = acc[i][0] + bias[0];
        o.y = acc[i][1] + bias[1];
        o.z = acc[i][2] + bias[2];
        o.w = acc[i][3] + bias[3];
        *(float4*)&g_y3[gr*128 + tx*4] = o;
        cs[0] += o.x; cq[0] += o.x*o.x;
        cs[1] += o.y; cq[1] += o.y*o.y;
        cs[2] += o.z; cq[2] += o.z*o.z;
        cs[3] += o.w; cq[3] += o.w*o.w;
    }
#pragma unroll
    for (int j = 0; j < 4; j++) {
        atomicAdd(&ssum[tx*4+j], cs[j]);
        atomicAdd(&ssq [tx*4+j], cq[j]);
    }
    __syncthreads();
    if (tid < 128) {
        atomicAdd(&g_s3[tid], ssum[tid]);
        atomicAdd(&g_q3[tid], ssq[tid]);
    }
}

// ---------------------------------------------------------------------------
// 7) BN3 + ReLU + max over K + transpose to (B, 128, M)
// ---------------------------------------------------------------------------
__global__ void maxpool_kernel(float* __restrict__ out) {
    __shared__ float omax[32][129];
    __shared__ float a3s[128], c3s[128];
    int tid = threadIdx.x;
    int b  = blockIdx.x >> 6;
    int m0 = (blockIdx.x & 63) << 5;
    if (tid < 128) { a3s[tid] = g_a3[tid]; c3s[tid] = g_c3[tid]; }
    __syncthreads();

    for (int i = tid; i < 32*128; i += 256) {
        int c  = i & 127;
        int ml = i >> 7;
        const float* base = g_y3 + ((b*MM + m0 + ml) * KNbr) * 128 + c;
        float aa = a3s[c], cc = c3s[c];
        float mx = 0.f;                       // relu >= 0
#pragma unroll
        for (int k = 0; k < KNbr; k++)
            mx = fmaxf(mx, fmaf(aa, base[k*128], cc));
        omax[ml][c] = mx;
    }
    __syncthreads();
    for (int i = tid; i < 32*128; i += 256) {
        int c = i >> 5, j = i & 31;
        out[(b*128 + c)*MM + m0 + j] = omax[j][c];
    }
}

// ---------------------------------------------------------------------------
// launcher
// ---------------------------------------------------------------------------
extern "C" void kernel_launch(void* const* d_in, const int* in_sizes, int n_in,
                              void* d_out, int out_size) {
    const float* xyz   = (const float*)d_in[0];
    const float* feats = (const float*)d_in[1];
    const float* w1    = (const float*)d_in[2];
    const float* b1    = (const float*)d_in[3];
    const float* g1    = (const float*)d_in[4];
    const float* be1   = (const float*)d_in[5];
    const float* w2    = (const float*)d_in[6];
    const float* b2    = (const float*)d_in[7];
    const float* g2    = (const float*)d_in[8];
    const float* be2   = (const float*)d_in[9];
    const float* w3    = (const float*)d_in[10];
    const float* b3    = (const float*)d_in[11];
    const float* g3    = (const float*)d_in[12];
    const float* be3   = (const float*)d_in[13];

    float* out_centers = (float*)d_out;                 // (B, M, 3)
    float* out_feat    = out_centers + BB*MM*3;         // (B, 128, M)

    const int knn_smem = 2 * PP * (int)sizeof(float);   // 64 KB
    cudaFuncSetAttribute(knn_kernel, cudaFuncAttributeMaxDynamicSharedMemorySize,
                         knn_smem);

    init_stats_kernel<<<1, 128>>>();

    dim3 tb(32, 8), tg(PP/32, CC/32, BB);
    transpose_kernel<<<tg, tb>>>(feats);

    knn_kernel<<<BB*MM/2, 256, knn_smem>>>(xyz, out_centers);

    gemm1_kernel<<<RR/64, 128>>>(xyz, w1, b1);
    finalize_kernel<<<1, 128>>>(g1, be1, 1);

    gemm2_kernel<<<RR/64, 128>>>(w2, b2);
    finalize_kernel<<<1, 128>>>(g2, be2, 2);

    gemm3_kernel<<<RR/32, 256>>>(w3, b3);
    finalize_kernel<<<1, 128>>>(g3, be3, 3);

    maxpool_kernel<<<BB*MM/32, 256>>>(out_feat);
}

// round 2
// speedup vs baseline: 2.1051x; 2.1051x over previous
#include <cuda_runtime.h>
#include <cuda_bf16.h>

// ---------------------------------------------------------------------------
// Problem constants
// ---------------------------------------------------------------------------
#define BB   8
#define PP   8192
#define CC   64
#define MM   2048          // P/4 centers
#define KNbr 32            // NSAMPLE
#define RR   (BB*MM*KNbr)  // 524288 rows
#define BN_EPS 1e-5f

// ---------------------------------------------------------------------------
// Device scratch (static __device__ arrays: allocation-free)
// ---------------------------------------------------------------------------
__device__ float g_fT  [BB*PP*CC];       // feats transposed (B,P,C)     16 MB
__device__ int   g_idx [RR];             // knn indices                   2 MB
__device__ float g_y1  [64*RR];          // layer1 pre-BN, channel-major 134 MB
__device__ float g_y2  [64*RR];          // layer2 pre-BN, channel-major 134 MB
__device__ float g_pool[BB*MM*128];      // pooled pre-BN layer3 max      4 MB

__device__ float g_s1[64],  g_q1[64],  g_a1[64],  g_c1[64];
__device__ float g_s2[64],  g_q2[64],  g_a2[64],  g_c2[64];
__device__ float g_s3[128], g_q3[128], g_a3[128], g_c3[128];

// ---------------------------------------------------------------------------
// helpers
// ---------------------------------------------------------------------------
__device__ __forceinline__ unsigned long long shfl64(unsigned long long v, int src) {
    unsigned lo = __shfl_sync(0xffffffffu, (unsigned)(v & 0xffffffffu), src);
    unsigned hi = __shfl_sync(0xffffffffu, (unsigned)(v >> 32), src);
    return ((unsigned long long)hi << 32) | lo;
}
__device__ __forceinline__ unsigned long long warpmax64(unsigned long long v) {
#pragma unroll
    for (int s = 16; s; s >>= 1) {
        unsigned lo = __shfl_xor_sync(0xffffffffu, (unsigned)(v & 0xffffffffu), s);
        unsigned hi = __shfl_xor_sync(0xffffffffu, (unsigned)(v >> 32), s);
        unsigned long long o = ((unsigned long long)hi << 32) | lo;
        if (o > v) v = o;
    }
    return v;
}
// order-preserving float <-> unsigned for atomicMax on floats (any sign)
__device__ __forceinline__ unsigned fenc(float f) {
    unsigned u = __float_as_uint(f);
    return (u & 0x80000000u) ? ~u : (u | 0x80000000u);
}
__device__ __forceinline__ float fdec(unsigned u) {
    return __uint_as_float((u & 0x80000000u) ? (u & 0x7fffffffu) : ~u);
}

// ---------------------------------------------------------------------------
// 0) zero BN stat accumulators (fresh state per graph replay)
// ---------------------------------------------------------------------------
__global__ void init_stats_kernel() {
    int i = threadIdx.x;
    if (i < 64)  { g_s1[i] = 0.f; g_q1[i] = 0.f; g_s2[i] = 0.f; g_q2[i] = 0.f; }
    if (i < 128) { g_s3[i] = 0.f; g_q3[i] = 0.f; }
}

// ---------------------------------------------------------------------------
// 1) transpose feats (B,C,P) -> (B,P,C)
// ---------------------------------------------------------------------------
__global__ void transpose_kernel(const float* __restrict__ feats) {
    __shared__ float tile[32][33];
    int b  = blockIdx.z;
    int c0 = blockIdx.y * 32;
    int p0 = blockIdx.x * 32;
    int tx = threadIdx.x, ty = threadIdx.y;
    const float* src = feats + (b*CC + c0)*PP + p0;
#pragma unroll
    for (int i = 0; i < 32; i += 8)
        tile[ty+i][tx] = src[(ty+i)*PP + tx];
    __syncthreads();
    float* dst = g_fT + (b*PP + p0)*CC + c0;
#pragma unroll
    for (int i = 0; i < 32; i += 8)
        dst[(ty+i)*CC + tx] = tile[tx][ty+i];
}

// ---------------------------------------------------------------------------
// 2) centers + exact 32-NN. 8 warps/block, one center per warp.
//    Register-resident top-32: one (d2,idx) u64 key per lane; ballot-driven
//    insertion replacing the current worst. xyz streamed via smem chunks.
// ---------------------------------------------------------------------------
#define KCHUNK 2048
__global__ __launch_bounds__(256) void knn_kernel(const float* __restrict__ xyz,
                                                  float* __restrict__ out_centers) {
    __shared__ float sp[KCHUNK*3];                 // 24 KB
    int lane = threadIdx.x & 31, warp = threadIdx.x >> 5;
    int b = blockIdx.x >> 8;                       // 256 blocks per batch
    int m = ((blockIdx.x & 255) << 3) | warp;
    const float* xb = xyz + b*PP*3;
    int pc = (int)((float)m * (8191.0f/2047.0f));
    float cx = xb[pc*3+0], cy = xb[pc*3+1], cz = xb[pc*3+2];
    if (lane < 3) out_centers[(b*MM + m)*3 + lane] = xb[pc*3 + lane];

    unsigned long long key = 0ull, worst = 0ull;
    for (int base = 0; base < PP; base += KCHUNK) {
        __syncthreads();
        for (int u = threadIdx.x; u < KCHUNK*3; u += 256)
            sp[u] = xb[base*3 + u];
        __syncthreads();
#pragma unroll 1
        for (int s = 0; s < KCHUNK; s += 32) {
            int t = s + lane;
            float dx = sp[3*t+0] - cx, dy = sp[3*t+1] - cy, dz = sp[3*t+2] - cz;
            float d2 = fmaf(dx, dx, fmaf(dy, dy, dz*dz));
            unsigned long long cand =
                ((unsigned long long)__float_as_uint(d2) << 32) | (unsigned)(base + t);
            if (base == 0 && s == 0) {             // first 32 points seed the set
                key = cand;
                worst = warpmax64(key);
                continue;
            }
            unsigned mask = __ballot_sync(0xffffffffu, cand < worst);
            while (mask) {
                int l = __ffs(mask) - 1; mask &= mask - 1;
                unsigned long long ck = shfl64(cand, l);
                if (ck < worst) {
                    unsigned em = __ballot_sync(0xffffffffu, key == worst);
                    int rl = __ffs(em) - 1;        // lowest lane holding worst
                    if (lane == rl) key = ck;
                    worst = warpmax64(key);
                }
            }
        }
    }
    g_idx[((b*MM + m) << 5) | lane] = (int)(unsigned)(key & 0xffffffffu);
}

// ---------------------------------------------------------------------------
// 3) GEMM1: gather [feats(64)|local_xyz(3)] -> As[k][row] (transposed smem),
//    x W1^T + b1 -> y1 channel-major [64][RR], stats.
//    128 thr, tile 128x64, thread = 8x8, float4 LDS both operands.
// ---------------------------------------------------------------------------
__global__ __launch_bounds__(128) void gemm1_kernel(const float* __restrict__ xyz,
                                                    const float* __restrict__ w1,
                                                    const float* __restrict__ b1) {
    extern __shared__ float sm[];
    float* As   = sm;                   // [67][132]
    float* Ws   = sm + 67*132;          // [67][68]
    float* ssum = Ws + 67*68;           // [64]
    float* ssq  = ssum + 64;            // [64]
    int tid = threadIdx.x;
    int rowbase = blockIdx.x << 7;

    if (tid < 64) { ssum[tid] = 0.f; ssq[tid] = 0.f; }
    for (int i = tid; i < 67*64; i += 128) {
        int k = i >> 6, o = i & 63;
        int ch = (k < 64) ? (k + 3) : (k - 64);   // feats first, xyz last
        Ws[k*68 + o] = w1[o*67 + ch];
    }
    {   // gather one row per thread, store transposed
        int gr  = rowbase + tid;
        int b   = gr >> 16;
        int m   = (gr >> 5) & (MM - 1);
        int idx = g_idx[gr];
        const float4* frow = (const float4*)(g_fT + (((b << 13) + idx) << 6));
#pragma unroll
        for (int q = 0; q < 16; q++) {
            float4 v = frow[q];
            As[(q*4+0)*132 + tid] = v.x;
            As[(q*4+1)*132 + tid] = v.y;
            As[(q*4+2)*132 + tid] = v.z;
            As[(q*4+3)*132 + tid] = v.w;
        }
        int pcc = (int)((float)m * (8191.0f/2047.0f));
        const float* x = xyz + b*PP*3;
        As[64*132 + tid] = x[idx*3+0] - x[pcc*3+0];
        As[65*132 + tid] = x[idx*3+1] - x[pcc*3+1];
        As[66*132 + tid] = x[idx*3+2] - x[pcc*3+2];
    }
    __syncthreads();

    int tx = tid & 7, ty = tid >> 3;
    float acc[8][8];
#pragma unroll
    for (int i = 0; i < 8; i++)
#pragma unroll
        for (int j = 0; j < 8; j++) acc[i][j] = 0.f;

#pragma unroll 4
    for (int k = 0; k < 67; k++) {
        float4 a0 = *(const float4*)&As[k*132 + ty*8];
        float4 a1 = *(const float4*)&As[k*132 + ty*8 + 4];
        float4 b0 = *(const float4*)&Ws[k*68 + tx*8];
        float4 b4 = *(const float4*)&Ws[k*68 + tx*8 + 4];
        float av[8] = {a0.x,a0.y,a0.z,a0.w,a1.x,a1.y,a1.z,a1.w};
        float bv[8] = {b0.x,b0.y,b0.z,b0.w,b4.x,b4.y,b4.z,b4.w};
#pragma unroll
        for (int i = 0; i < 8; i++)
#pragma unroll
            for (int j = 0; j < 8; j++)
                acc[i][j] = fmaf(av[i], bv[j], acc[i][j]);
    }

    float cs[8], cq[8];
#pragma unroll
    for (int j = 0; j < 8; j++) {
        float bb = b1[tx*8 + j];
        float s = 0.f, q = 0.f;
#pragma unroll
        for (int i = 0; i < 8; i++) {
            acc[i][j] += bb;
            s += acc[i][j];
            q  = fmaf(acc[i][j], acc[i][j], q);
        }
        cs[j] = s; cq[j] = q;
        float* dst = g_y1 + (tx*8 + j)*RR + rowbase + ty*8;
        float4 v0 = {acc[0][j], acc[1][j], acc[2][j], acc[3][j]};
        float4 v1 = {acc[4][j], acc[5][j], acc[6][j], acc[7][j]};
        *(float4*)dst       = v0;
        *(float4*)(dst + 4) = v1;
    }
#pragma unroll
    for (int j = 0; j < 8; j++) {
        cs[j] += __shfl_xor_sync(0xffffffffu, cs[j], 8);
        cq[j] += __shfl_xor_sync(0xffffffffu, cq[j], 8);
        cs[j] += __shfl_xor_sync(0xffffffffu, cs[j], 16);
        cq[j] += __shfl_xor_sync(0xffffffffu, cq[j], 16);
    }
    if ((tid & 31) < 8) {
#pragma unroll
        for (int j = 0; j < 8; j++) {
            atomicAdd(&ssum[tx*8 + j], cs[j]);
            atomicAdd(&ssq [tx*8 + j], cq[j]);
        }
    }
    __syncthreads();
    if (tid < 64) { atomicAdd(&g_s1[tid], ssum[tid]); atomicAdd(&g_q1[tid], ssq[tid]); }
}

// ---------------------------------------------------------------------------
// 4) BN finalize: a = g*rsqrt(var+eps), c = beta - mean*a
// ---------------------------------------------------------------------------
__global__ void finalize_kernel(const float* __restrict__ g,
                                const float* __restrict__ beta, int layer) {
    int i = threadIdx.x;
    float *s, *q, *a, *c; int n;
    if (layer == 1)      { s = g_s1; q = g_q1; a = g_a1; c = g_c1; n = 64;  }
    else if (layer == 2) { s = g_s2; q = g_q2; a = g_a2; c = g_c2; n = 64;  }
    else                 { s = g_s3; q = g_q3; a = g_a3; c = g_c3; n = 128; }
    if (i < n) {
        const float invN = 1.0f / (float)RR;
        float mean = s[i] * invN;
        float var  = fmaxf(q[i] * invN - mean*mean, 0.f);
        float inv  = rsqrtf(var + BN_EPS);
        float aa   = g[i] * inv;
        a[i] = aa;
        c[i] = beta[i] - mean * aa;
    }
}

// ---------------------------------------------------------------------------
// 5) GEMM2: x = relu(a1*y1+c1) (channel-major load, all float4);
//    y2 = x W2^T + b2 channel-major; stats.
// ---------------------------------------------------------------------------
__global__ __launch_bounds__(128) void gemm2_kernel(const float* __restrict__ w2,
                                                    const float* __restrict__ b2) {
    extern __shared__ float sm[];
    float* As   = sm;                   // [64][132]
    float* Ws   = sm + 64*132;          // [64][68]
    float* ssum = Ws + 64*68;
    float* ssq  = ssum + 64;
    int tid = threadIdx.x;
    int rowbase = blockIdx.x << 7;

    if (tid < 64) { ssum[tid] = 0.f; ssq[tid] = 0.f; }
    for (int i = tid; i < 64*64; i += 128) {
        int k = i >> 6, o = i & 63;
        Ws[k*68 + o] = w2[o*64 + k];
    }
#pragma unroll
    for (int chunk = 0; chunk < 16; chunk++) {
        int lin = chunk*128 + tid;
        int k = lin >> 5, r4 = lin & 31;
        float a = g_a1[k], c = g_c1[k];
        float4 v = *(const float4*)(g_y1 + k*RR + rowbase + r4*4);
        v.x = fmaxf(fmaf(a, v.x, c), 0.f);
        v.y = fmaxf(fmaf(a, v.y, c), 0.f);
        v.z = fmaxf(fmaf(a, v.z, c), 0.f);
        v.w = fmaxf(fmaf(a, v.w, c), 0.f);
        *(float4*)&As[k*132 + r4*4] = v;
    }
    __syncthreads();

    int tx = tid & 7, ty = tid >> 3;
    float acc[8][8];
#pragma unroll
    for (int i = 0; i < 8; i++)
#pragma unroll
        for (int j = 0; j < 8; j++) acc[i][j] = 0.f;

#pragma unroll 4
    for (int k = 0; k < 64; k++) {
        float4 a0 = *(const float4*)&As[k*132 + ty*8];
        float4 a1 = *(const float4*)&As[k*132 + ty*8 + 4];
        float4 b0 = *(const float4*)&Ws[k*68 + tx*8];
        float4 b4 = *(const float4*)&Ws[k*68 + tx*8 + 4];
        float av[8] = {a0.x,a0.y,a0.z,a0.w,a1.x,a1.y,a1.z,a1.w};
        float bv[8] = {b0.x,b0.y,b0.z,b0.w,b4.x,b4.y,b4.z,b4.w};
#pragma unroll
        for (int i = 0; i < 8; i++)
#pragma unroll
            for (int j = 0; j < 8; j++)
                acc[i][j] = fmaf(av[i], bv[j], acc[i][j]);
    }

    float cs[8], cq[8];
#pragma unroll
    for (int j = 0; j < 8; j++) {
        float bb = b2[tx*8 + j];
        float s = 0.f, q = 0.f;
#pragma unroll
        for (int i = 0; i < 8; i++) {
            acc[i][j] += bb;
            s += acc[i][j];
            q  = fmaf(acc[i][j], acc[i][j], q);
        }
        cs[j] = s; cq[j] = q;
        float* dst = g_y2 + (tx*8 + j)*RR + rowbase + ty*8;
        float4 v0 = {acc[0][j], acc[1][j], acc[2][j], acc[3][j]};
        float4 v1 = {acc[4][j], acc[5][j], acc[6][j], acc[7][j]};
        *(float4*)dst       = v0;
        *(float4*)(dst + 4) = v1;
    }
#pragma unroll
    for (int j = 0; j < 8; j++) {
        cs[j] += __shfl_xor_sync(0xffffffffu, cs[j], 8);
        cq[j] += __shfl_xor_sync(0xffffffffu, cq[j], 8);
        cs[j] += __shfl_xor_sync(0xffffffffu, cs[j], 16);
        cq[j] += __shfl_xor_sync(0xffffffffu, cq[j], 16);
    }
    if ((tid & 31) < 8) {
#pragma unroll
        for (int j = 0; j < 8; j++) {
            atomicAdd(&ssum[tx*8 + j], cs[j]);
            atomicAdd(&ssq [tx*8 + j], cq[j]);
        }
    }
    __syncthreads();
    if (tid < 64) { atomicAdd(&g_s2[tid], ssum[tid]); atomicAdd(&g_q2[tid], ssq[tid]); }
}

// ---------------------------------------------------------------------------
// 6) GEMM3 + fused max-pool: x = relu(a2*y2+c2); y3 = x W3^T + b3.
//    Tile 128 rows (= 4 centers) x 128 cols, 256 thr, 8x8/thread.
//    Pools max_k(y3) per center in-block (a3>0 makes BN+relu commute with max)
//    -> writes 4 MB g_pool instead of 268 MB y3. Stats accumulated too.
// ---------------------------------------------------------------------------
__global__ __launch_bounds__(256) void gemm3_kernel(const float* __restrict__ w3,
                                                    const float* __restrict__ b3) {
    extern __shared__ float sm[];
    float*    As    = sm;                     // [64][132]
    float*    Ws    = sm + 64*132;            // [64][132]
    unsigned* pmaxu = (unsigned*)(sm + 2*64*132);  // [4][128]
    float*    ssum  = sm + 2*64*132 + 512;    // [128]
    float*    ssq   = ssum + 128;             // [128]
    int tid = threadIdx.x;
    int rowbase = blockIdx.x << 7;

    if (tid < 128) { ssum[tid] = 0.f; ssq[tid] = 0.f; }
    for (int i = tid; i < 512; i += 256) pmaxu[i] = 0u;   // below all encoded reals
    for (int i = tid; i < 64*128; i += 256) {
        int k = i >> 7, o = i & 127;
        Ws[k*132 + o] = w3[o*64 + k];
    }
#pragma unroll
    for (int chunk = 0; chunk < 8; chunk++) {
        int lin = chunk*256 + tid;
        int k = lin >> 5, r4 = lin & 31;
        float a = g_a2[k], c = g_c2[k];
        float4 v = *(const float4*)(g_y2 + k*RR + rowbase + r4*4);
        v.x = fmaxf(fmaf(a, v.x, c), 0.f);
        v.y = fmaxf(fmaf(a, v.y, c), 0.f);
        v.z = fmaxf(fmaf(a, v.z, c), 0.f);
        v.w = fmaxf(fmaf(a, v.w, c), 0.f);
        *(float4*)&As[k*132 + r4*4] = v;
    }
    __syncthreads();

    int tx = tid & 15, ty = tid >> 4;
    float acc[8][8];
#pragma unroll
    for (int i = 0; i < 8; i++)
#pragma unroll
        for (int j = 0; j < 8; j++) acc[i][j] = 0.f;

#pragma unroll 4
    for (int k = 0; k < 64; k++) {
        float4 a0 = *(const float4*)&As[k*132 + ty*8];
        float4 a1 = *(const float4*)&As[k*132 + ty*8 + 4];
        float4 b0 = *(const float4*)&Ws[k*132 + tx*8];
        float4 b4 = *(const float4*)&Ws[k*132 + tx*8 + 4];
        float av[8] = {a0.x,a0.y,a0.z,a0.w,a1.x,a1.y,a1.z,a1.w};
        float bv[8] = {b0.x,b0.y,b0.z,b0.w,b4.x,b4.y,b4.z,b4.w};
#pragma unroll
        for (int i = 0; i < 8; i++)
#pragma unroll
            for (int j = 0; j < 8; j++)
                acc[i][j] = fmaf(av[i], bv[j], acc[i][j]);
    }

    int center = ty >> 2;                      // thread's 8 rows stay in one center
    float cs[8], cq[8];
#pragma unroll
    for (int j = 0; j < 8; j++) {
        int col = tx*8 + j;
        float bb = b3[col];
        float s = 0.f, q = 0.f, mx = -3.4e38f;
#pragma unroll
        for (int i = 0; i < 8; i++) {
            float v = acc[i][j] + bb;
            s += v;
            q  = fmaf(v, v, q);
            mx = fmaxf(mx, v);
        }
        cs[j] = s; cq[j] = q;
        atomicMax(&pmaxu[center*128 + col], fenc(mx));
    }
#pragma unroll
    for (int j = 0; j < 8; j++) {              // combine the 2 ty-groups per warp
        cs[j] += __shfl_xor_sync(0xffffffffu, cs[j], 16);
        cq[j] += __shfl_xor_sync(0xffffffffu, cq[j], 16);
    }
    if ((tid & 31) < 16) {
#pragma unroll
        for (int j = 0; j < 8; j++) {
            atomicAdd(&ssum[tx*8 + j], cs[j]);
            atomicAdd(&ssq [tx*8 + j], cq[j]);
        }
    }
    __syncthreads();
    if (tid < 128) { atomicAdd(&g_s3[tid], ssum[tid]); atomicAdd(&g_q3[tid], ssq[tid]); }
    for (int i = tid; i < 512; i += 256) {
        int cl = i >> 7, c = i & 127;
        g_pool[(blockIdx.x*4 + cl)*128 + c] = fdec(pmaxu[cl*128 + c]);
    }
}

// ---------------------------------------------------------------------------
// 7) BN3 + ReLU on pooled maxima + transpose to (B, 128, M). 4 MB only.
// ---------------------------------------------------------------------------
__global__ __launch_bounds__(256) void out3_kernel(float* __restrict__ out) {
    __shared__ float t[32][129];
    __shared__ float a3s[128], c3s[128];
    int tid = threadIdx.x;
    int b  = blockIdx.x >> 6;
    int m0 = (blockIdx.x & 63) << 5;
    if (tid < 128) { a3s[tid] = g_a3[tid]; c3s[tid] = g_c3[tid]; }
    __syncthreads();
    for (int i = tid; i < 32*128; i += 256) {
        int ml = i >> 7, c = i & 127;
        float v = g_pool[((b*MM + m0 + ml) << 7) + c];
        t[ml][c] = fmaxf(fmaf(a3s[c], v, c3s[c]), 0.f);
    }
    __syncthreads();
    for (int i = tid; i < 32*128; i += 256) {
        int c = i >> 5, j = i & 31;
        out[(b*128 + c)*MM + m0 + j] = t[j][c];
    }
}

// ---------------------------------------------------------------------------
// launcher
// ---------------------------------------------------------------------------
extern "C" void kernel_launch(void* const* d_in, const int* in_sizes, int n_in,
                              void* d_out, int out_size) {
    const float* xyz   = (const float*)d_in[0];
    const float* feats = (const float*)d_in[1];
    const float* w1    = (const float*)d_in[2];
    const float* b1    = (const float*)d_in[3];
    const float* g1    = (const float*)d_in[4];
    const float* be1   = (const float*)d_in[5];
    const float* w2    = (const float*)d_in[6];
    const float* b2    = (const float*)d_in[7];
    const float* g2    = (const float*)d_in[8];
    const float* be2   = (const float*)d_in[9];
    const float* w3    = (const float*)d_in[10];
    const float* b3    = (const float*)d_in[11];
    const float* g3    = (const float*)d_in[12];
    const float* be3   = (const float*)d_in[13];

    float* out_centers = (float*)d_out;                 // (B, M, 3)
    float* out_feat    = out_centers + BB*MM*3;         // (B, 128, M)

    const int smem1 = (67*132 + 67*68 + 128) * 4;       // 54,112 B
    const int smem2 = (64*132 + 64*68 + 128) * 4;       // 51,712 B
    const int smem3 = (2*64*132 + 512 + 256) * 4;       // 70,656 B
    cudaFuncSetAttribute(gemm1_kernel, cudaFuncAttributeMaxDynamicSharedMemorySize, smem1);
    cudaFuncSetAttribute(gemm2_kernel, cudaFuncAttributeMaxDynamicSharedMemorySize, smem2);
    cudaFuncSetAttribute(gemm3_kernel, cudaFuncAttributeMaxDynamicSharedMemorySize, smem3);

    init_stats_kernel<<<1, 128>>>();

    dim3 tb(32, 8), tg(PP/32, CC/32, BB);
    transpose_kernel<<<tg, tb>>>(feats);

    knn_kernel<<<BB*MM/8, 256>>>(xyz, out_centers);

    gemm1_kernel<<<RR/128, 128, smem1>>>(xyz, w1, b1);
    finalize_kernel<<<1, 128>>>(g1, be1, 1);

    gemm2_kernel<<<RR/128, 128, smem2>>>(w2, b2);
    finalize_kernel<<<1, 128>>>(g2, be2, 2);

    gemm3_kernel<<<RR/128, 256, smem3>>>(w3, b3);
    finalize_kernel<<<1, 128>>>(g3, be3, 3);

    out3_kernel<<<BB*MM/32, 256>>>(out_feat);
}

// round 4
// speedup vs baseline: 2.8763x; 1.3663x over previous
#include <cuda_runtime.h>
#include <cuda_bf16.h>
#include <stdint.h>

// ---------------------------------------------------------------------------
// Problem constants
// ---------------------------------------------------------------------------
#define BB   8
#define PP   8192
#define CC   64
#define MM   2048
#define KNbr 32
#define RR   (BB*MM*KNbr)  // 524288 rows
#define BN_EPS 1e-5f

// ---------------------------------------------------------------------------
// Device scratch
// ---------------------------------------------------------------------------
__device__ float g_fT  [BB*PP*CC];       // feats transposed (B,P,C)
__device__ int   g_idx [RR];             // knn indices
__device__ float g_y1  [64*RR];          // layer1 pre-BN, channel-major
__device__ float g_y2  [64*RR];          // layer2 pre-BN, channel-major
__device__ float g_pool[BB*MM*128];      // pooled pre-BN layer3 max

__device__ float g_s1[64],  g_q1[64],  g_a1[64],  g_c1[64];
__device__ float g_s2[64],  g_q2[64],  g_a2[64],  g_c2[64];
__device__ float g_s3[128], g_q3[128], g_a3[128], g_c3[128];

// fragmentized weights: per (ntile,kstep,lane) a uint4 {bh0,bh1,bl0,bl1}
__device__ uint4 g_bf1[1024];   // 64 out
__device__ uint4 g_bf2[1024];   // 64 out
__device__ uint4 g_bf3[2048];   // 128 out

// ---------------------------------------------------------------------------
// helpers
// ---------------------------------------------------------------------------
__device__ __forceinline__ void mma16816(float* d, const uint32_t* a,
                                         uint32_t b0, uint32_t b1) {
    asm volatile(
        "mma.sync.aligned.m16n8k16.row.col.f32.bf16.bf16.f32 "
        "{%0,%1,%2,%3}, {%4,%5,%6,%7}, {%8,%9}, {%0,%1,%2,%3};"
        : "+f"(d[0]), "+f"(d[1]), "+f"(d[2]), "+f"(d[3])
        : "r"(a[0]), "r"(a[1]), "r"(a[2]), "r"(a[3]), "r"(b0), "r"(b1));
}
__device__ __forceinline__ uint32_t pack_bf16(float lo, float hi) {
    __nv_bfloat162 h2 = __floats2bfloat162_rn(lo, hi);
    return *reinterpret_cast<uint32_t*>(&h2);
}
__device__ __forceinline__ void split2(float f0, float f1,
                                       uint32_t& hi, uint32_t& lo) {
    __nv_bfloat162 h2 = __floats2bfloat162_rn(f0, f1);
    float2 hf = __bfloat1622float2(h2);
    __nv_bfloat162 l2 = __floats2bfloat162_rn(f0 - hf.x, f1 - hf.y);
    hi = *reinterpret_cast<uint32_t*>(&h2);
    lo = *reinterpret_cast<uint32_t*>(&l2);
}
__device__ __forceinline__ float rsum_g(float v) {
    v += __shfl_xor_sync(0xffffffffu, v, 4);
    v += __shfl_xor_sync(0xffffffffu, v, 8);
    v += __shfl_xor_sync(0xffffffffu, v, 16);
    return v;
}
__device__ __forceinline__ float rmax_g(float v) {
    v = fmaxf(v, __shfl_xor_sync(0xffffffffu, v, 4));
    v = fmaxf(v, __shfl_xor_sync(0xffffffffu, v, 8));
    v = fmaxf(v, __shfl_xor_sync(0xffffffffu, v, 16));
    return v;
}
__device__ __forceinline__ unsigned fenc(float f) {
    unsigned u = __float_as_uint(f);
    return (u & 0x80000000u) ? ~u : (u | 0x80000000u);
}
__device__ __forceinline__ float fdec(unsigned u) {
    return __uint_as_float((u & 0x80000000u) ? (u & 0x7fffffffu) : ~u);
}
__device__ __forceinline__ unsigned long long shfl64(unsigned long long v, int src) {
    unsigned lo = __shfl_sync(0xffffffffu, (unsigned)(v & 0xffffffffu), src);
    unsigned hi = __shfl_sync(0xffffffffu, (unsigned)(v >> 32), src);
    return ((unsigned long long)hi << 32) | lo;
}
__device__ __forceinline__ unsigned long long warpmax64(unsigned long long v) {
#pragma unroll
    for (int s = 16; s; s >>= 1) {
        unsigned lo = __shfl_xor_sync(0xffffffffu, (unsigned)(v & 0xffffffffu), s);
        unsigned hi = __shfl_xor_sync(0xffffffffu, (unsigned)(v >> 32), s);
        unsigned long long o = ((unsigned long long)hi << 32) | lo;
        if (o > v) v = o;
    }
    return v;
}

// ---------------------------------------------------------------------------
// 0) init + fragmentized weight prep
// ---------------------------------------------------------------------------
__global__ void init_stats_kernel() {
    int i = threadIdx.x;
    if (i < 64)  { g_s1[i] = 0.f; g_q1[i] = 0.f; g_s2[i] = 0.f; g_q2[i] = 0.f; }
    if (i < 128) { g_s3[i] = 0.f; g_q3[i] = 0.f; }
}

__global__ void prep_w_kernel(const float* __restrict__ w1,
                              const float* __restrict__ w2,
                              const float* __restrict__ w3) {
    int t = blockIdx.x * blockDim.x + threadIdx.x;   // 4096
    const float* src; uint4* dst; int ld, off, e;
    if (t < 1024)      { e = t;        src = w1; dst = g_bf1; ld = 67; off = 3; }
    else if (t < 2048) { e = t - 1024; src = w2; dst = g_bf2; ld = 64; off = 0; }
    else               { e = t - 2048; src = w3; dst = g_bf3; ld = 64; off = 0; }
    int l  = e & 31;
    int ks = (e >> 5) & 3;
    int nt = e >> 7;
    int n  = nt*8 + (l >> 2);
    int k0 = ks*16 + 2*(l & 3);
    const float* wr = src + n*ld + off;
    uint4 o4;
    uint32_t h, lo2;
    split2(wr[k0],   wr[k0+1], h, lo2);  o4.x = h; o4.z = lo2;
    split2(wr[k0+8], wr[k0+9], h, lo2);  o4.y = h; o4.w = lo2;
    dst[e] = o4;
}

// ---------------------------------------------------------------------------
// 1) transpose feats (B,C,P) -> (B,P,C)
// ---------------------------------------------------------------------------
__global__ void transpose_kernel(const float* __restrict__ feats) {
    __shared__ float tile[32][33];
    int b  = blockIdx.z;
    int c0 = blockIdx.y * 32;
    int p0 = blockIdx.x * 32;
    int tx = threadIdx.x, ty = threadIdx.y;
    const float* src = feats + (b*CC + c0)*PP + p0;
#pragma unroll
    for (int i = 0; i < 32; i += 8)
        tile[ty+i][tx] = src[(ty+i)*PP + tx];
    __syncthreads();
    float* dst = g_fT + (b*PP + p0)*CC + c0;
#pragma unroll
    for (int i = 0; i < 32; i += 8)
        dst[(ty+i)*CC + tx] = tile[tx][ty+i];
}

// ---------------------------------------------------------------------------
// 2) exact 32-NN (warp per center, register top-32)
// ---------------------------------------------------------------------------
#define KCHUNK 2048
__global__ __launch_bounds__(256) void knn_kernel(const float* __restrict__ xyz,
                                                  float* __restrict__ out_centers) {
    __shared__ float sp[KCHUNK*3];
    int lane = threadIdx.x & 31, warp = threadIdx.x >> 5;
    int b = blockIdx.x >> 8;
    int m = ((blockIdx.x & 255) << 3) | warp;
    const float* xb = xyz + b*PP*3;
    int pc = (int)((float)m * (8191.0f/2047.0f));
    float cx = xb[pc*3+0], cy = xb[pc*3+1], cz = xb[pc*3+2];
    if (lane < 3) out_centers[(b*MM + m)*3 + lane] = xb[pc*3 + lane];

    unsigned long long key = 0ull, worst = 0ull;
    for (int base = 0; base < PP; base += KCHUNK) {
        __syncthreads();
        for (int u = threadIdx.x; u < KCHUNK*3; u += 256)
            sp[u] = xb[base*3 + u];
        __syncthreads();
#pragma unroll 1
        for (int s = 0; s < KCHUNK; s += 32) {
            int t = s + lane;
            float dx = sp[3*t+0] - cx, dy = sp[3*t+1] - cy, dz = sp[3*t+2] - cz;
            float d2 = fmaf(dx, dx, fmaf(dy, dy, dz*dz));
            unsigned long long cand =
                ((unsigned long long)__float_as_uint(d2) << 32) | (unsigned)(base + t);
            if (base == 0 && s == 0) {
                key = cand;
                worst = warpmax64(key);
                continue;
            }
            unsigned mask = __ballot_sync(0xffffffffu, cand < worst);
            while (mask) {
                int l = __ffs(mask) - 1; mask &= mask - 1;
                unsigned long long ck = shfl64(cand, l);
                if (ck < worst) {
                    unsigned em = __ballot_sync(0xffffffffu, key == worst);
                    int rl = __ffs(em) - 1;
                    if (lane == rl) key = ck;
                    worst = warpmax64(key);
                }
            }
        }
    }
    g_idx[((b*MM + m) << 5) | lane] = (int)(unsigned)(key & 0xffffffffu);
}

// ---------------------------------------------------------------------------
// 3) Layer 1: gather + HMMA (feats 64ch) + exact fp32 xyz side-channel.
//    128 rows/block, 256 thr (8 warps x 16 rows). bf16 hi/lo split, 3 MMAs.
// ---------------------------------------------------------------------------
__global__ __launch_bounds__(256) void mlp1_kernel(const float* __restrict__ xyz,
                                                   const float* __restrict__ w1,
                                                   const float* __restrict__ b1) {
    __shared__ uint32_t Ah[128][32];        // bf16x2, swizzled col=(kp+4r)&31
    __shared__ uint32_t Al[128][32];
    __shared__ float lxs[3][128];
    __shared__ float wxs[3][64];
    __shared__ float ssm[64], sqm[64];

    int tid = threadIdx.x, w = tid >> 5, l = tid & 31;
    int gq = l >> 2, tg = l & 3;
    int rowbase = blockIdx.x << 7;

    if (tid < 64) { ssm[tid] = 0.f; sqm[tid] = 0.f; }
    if (tid < 192) {
        int c = tid >> 6, o = tid & 63;
        wxs[c][o] = w1[o*67 + c];
    }
    {   // fill: 2 threads per row
        int r = tid >> 1, h = tid & 1;
        int gr = rowbase + r;
        int b  = gr >> 16;
        int m  = (gr >> 5) & (MM - 1);
        int idx = g_idx[gr];
        const float4* frow = (const float4*)(g_fT + (((size_t)(b << 13) + idx) << 6));
#pragma unroll
        for (int q = 0; q < 8; q++) {
            float4 v = frow[h*8 + q];
            int kp = (h*8 + q)*2;
            uint32_t hi0, lo0, hi1, lo1;
            split2(v.x, v.y, hi0, lo0);
            split2(v.z, v.w, hi1, lo1);
            Ah[r][(kp   + 4*r) & 31] = hi0;
            Al[r][(kp   + 4*r) & 31] = lo0;
            Ah[r][(kp+1 + 4*r) & 31] = hi1;
            Al[r][(kp+1 + 4*r) & 31] = lo1;
        }
        if (h == 0) {
            int pcc = (int)((float)m * (8191.0f/2047.0f));
            const float* x = xyz + b*PP*3;
            lxs[0][r] = x[idx*3+0] - x[pcc*3+0];
            lxs[1][r] = x[idx*3+1] - x[pcc*3+1];
            lxs[2][r] = x[idx*3+2] - x[pcc*3+2];
        }
    }
    __syncthreads();

    int rg  = w*16 + gq;            // local rows rg, rg+8
    uint32_t ah[16], al[16];
#pragma unroll
    for (int ks = 0; ks < 4; ks++) {
        int c0 = ks*8 + tg;
        ah[ks*4+0] = Ah[rg  ][(c0   + 4*rg     ) & 31];
        ah[ks*4+1] = Ah[rg+8][(c0   + 4*(rg+8) ) & 31];
        ah[ks*4+2] = Ah[rg  ][(c0+4 + 4*rg     ) & 31];
        ah[ks*4+3] = Ah[rg+8][(c0+4 + 4*(rg+8) ) & 31];
        al[ks*4+0] = Al[rg  ][(c0   + 4*rg     ) & 31];
        al[ks*4+1] = Al[rg+8][(c0   + 4*(rg+8) ) & 31];
        al[ks*4+2] = Al[rg  ][(c0+4 + 4*rg     ) & 31];
        al[ks*4+3] = Al[rg+8][(c0+4 + 4*(rg+8) ) & 31];
    }

    float acc[8][4];
#pragma unroll
    for (int nt = 0; nt < 8; nt++)
#pragma unroll
        for (int j = 0; j < 4; j++) acc[nt][j] = 0.f;

#pragma unroll
    for (int nt = 0; nt < 8; nt++)
#pragma unroll
        for (int ks = 0; ks < 4; ks++) {
            uint4 bb = __ldg(&g_bf1[(nt*4 + ks)*32 + l]);
            mma16816(acc[nt], &ah[ks*4], bb.x, bb.y);
            mma16816(acc[nt], &al[ks*4], bb.x, bb.y);
            mma16816(acc[nt], &ah[ks*4], bb.z, bb.w);
        }

    int Rg = rowbase + rg;
    float lx0g = lxs[0][rg],   lx1g = lxs[1][rg],   lx2g = lxs[2][rg];
    float lx0h = lxs[0][rg+8], lx1h = lxs[1][rg+8], lx2h = lxs[2][rg+8];
#pragma unroll
    for (int nt = 0; nt < 8; nt++) {
        int c0 = nt*8 + 2*tg, c1 = c0 + 1;
        float bb0 = __ldg(&b1[c0]), bb1 = __ldg(&b1[c1]);
        float v00 = acc[nt][0] + bb0 + lx0g*wxs[0][c0] + lx1g*wxs[1][c0] + lx2g*wxs[2][c0];
        float v01 = acc[nt][1] + bb1 + lx0g*wxs[0][c1] + lx1g*wxs[1][c1] + lx2g*wxs[2][c1];
        float v10 = acc[nt][2] + bb0 + lx0h*wxs[0][c0] + lx1h*wxs[1][c0] + lx2h*wxs[2][c0];
        float v11 = acc[nt][3] + bb1 + lx0h*wxs[0][c1] + lx1h*wxs[1][c1] + lx2h*wxs[2][c1];
        g_y1[(size_t)c0*RR + Rg    ] = v00;
        g_y1[(size_t)c1*RR + Rg    ] = v01;
        g_y1[(size_t)c0*RR + Rg + 8] = v10;
        g_y1[(size_t)c1*RR + Rg + 8] = v11;
        float s0 = rsum_g(v00 + v10);
        float q0 = rsum_g(fmaf(v00, v00, v10*v10));
        float s1 = rsum_g(v01 + v11);
        float q1 = rsum_g(fmaf(v01, v01, v11*v11));
        if (l < 4) {
            atomicAdd(&ssm[c0], s0); atomicAdd(&sqm[c0], q0);
            atomicAdd(&ssm[c1], s1); atomicAdd(&sqm[c1], q1);
        }
    }
    __syncthreads();
    if (tid < 64) { atomicAdd(&g_s1[tid], ssm[tid]); atomicAdd(&g_q1[tid], sqm[tid]); }
}

// ---------------------------------------------------------------------------
// 4) Layers 2/3: BN+ReLU fused into fragment loads straight from global y
//    (channel-major => lane groups hit 8 consecutive rows = full sectors).
//    Layer 3: two 64-col halves + fused per-center max pool.
// ---------------------------------------------------------------------------
template<int LAYER>
__global__ __launch_bounds__(256) void mlp23_kernel(const float* __restrict__ bias) {
    constexpr int N = (LAYER == 3) ? 128 : 64;
    __shared__ float ssm[N], sqm[N];
    __shared__ unsigned pmax[4*128];

    int tid = threadIdx.x, w = tid >> 5, l = tid & 31;
    int gq = l >> 2, tg = l & 3;
    int rowbase = blockIdx.x << 7;
    int Rg = rowbase + w*16 + gq;

    if (tid < N) { ssm[tid] = 0.f; sqm[tid] = 0.f; }
    if (LAYER == 3) for (int i = tid; i < 512; i += 256) pmax[i] = 0u;
    __syncthreads();

    const float* ysrc = (LAYER == 2) ? g_y1 : g_y2;
    const float* ga   = (LAYER == 2) ? g_a1 : g_a2;
    const float* gc   = (LAYER == 2) ? g_c1 : g_c2;

    uint32_t ah[16], al[16];
#pragma unroll
    for (int ks = 0; ks < 4; ks++) {
        int kb = ks*16 + 2*tg;
#pragma unroll
        for (int half = 0; half < 2; half++) {
            int k0 = kb + half*8;
            float A0 = __ldg(&ga[k0]),   C0 = __ldg(&gc[k0]);
            float A1 = __ldg(&ga[k0+1]), C1 = __ldg(&gc[k0+1]);
            const float* y0 = ysrc + (size_t)k0*RR + Rg;
            const float* y1 = ysrc + (size_t)(k0+1)*RR + Rg;
            float f0 = fmaxf(fmaf(A0, y0[0], C0), 0.f);
            float f1 = fmaxf(fmaf(A1, y1[0], C1), 0.f);
            float f2 = fmaxf(fmaf(A0, y0[8], C0), 0.f);
            float f3 = fmaxf(fmaf(A1, y1[8], C1), 0.f);
            split2(f0, f1, ah[ks*4 + half*2 + 0], al[ks*4 + half*2 + 0]);
            split2(f2, f3, ah[ks*4 + half*2 + 1], al[ks*4 + half*2 + 1]);
        }
    }

    constexpr int HB = (LAYER == 3) ? 2 : 1;
#pragma unroll 1
    for (int hb = 0; hb < HB; hb++) {
        float acc[8][4];
#pragma unroll
        for (int nt = 0; nt < 8; nt++)
#pragma unroll
            for (int j = 0; j < 4; j++) acc[nt][j] = 0.f;

        const uint4* bfr = (LAYER == 2) ? g_bf2 : g_bf3;
#pragma unroll
        for (int nt = 0; nt < 8; nt++) {
            int ntg = hb*8 + nt;
#pragma unroll
            for (int ks = 0; ks < 4; ks++) {
                uint4 bb = __ldg(&bfr[(ntg*4 + ks)*32 + l]);
                mma16816(acc[nt], &ah[ks*4], bb.x, bb.y);
                mma16816(acc[nt], &al[ks*4], bb.x, bb.y);
                mma16816(acc[nt], &ah[ks*4], bb.z, bb.w);
            }
        }
#pragma unroll
        for (int nt = 0; nt < 8; nt++) {
            int c0 = hb*64 + nt*8 + 2*tg, c1 = c0 + 1;
            float v00 = acc[nt][0] + __ldg(&bias[c0]);
            float v01 = acc[nt][1] + __ldg(&bias[c1]);
            float v10 = acc[nt][2] + __ldg(&bias[c0]);
            float v11 = acc[nt][3] + __ldg(&bias[c1]);
            if (LAYER == 2) {
                g_y2[(size_t)c0*RR + Rg    ] = v00;
                g_y2[(size_t)c1*RR + Rg    ] = v01;
                g_y2[(size_t)c0*RR + Rg + 8] = v10;
                g_y2[(size_t)c1*RR + Rg + 8] = v11;
            }
            float s0 = rsum_g(v00 + v10);
            float q0 = rsum_g(fmaf(v00, v00, v10*v10));
            float s1 = rsum_g(v01 + v11);
            float q1 = rsum_g(fmaf(v01, v01, v11*v11));
            if (l < 4) {
                atomicAdd(&ssm[c0], s0); atomicAdd(&sqm[c0], q0);
                atomicAdd(&ssm[c1], s1); atomicAdd(&sqm[c1], q1);
            }
            if (LAYER == 3) {
                float m0 = rmax_g(fmaxf(v00, v10));
                float m1 = rmax_g(fmaxf(v01, v11));
                if (l < 4) {
                    atomicMax(&pmax[(w >> 1)*128 + c0], fenc(m0));
                    atomicMax(&pmax[(w >> 1)*128 + c1], fenc(m1));
                }
            }
        }
    }
    __syncthreads();
    float* gs = (LAYER == 2) ? g_s2 : g_s3;
    float* gq2 = (LAYER == 2) ? g_q2 : g_q3;
    if (tid < N) { atomicAdd(&gs[tid], ssm[tid]); atomicAdd(&gq2[tid], sqm[tid]); }
    if (LAYER == 3)
        for (int i = tid; i < 512; i += 256)
            g_pool[(size_t)blockIdx.x*512 + i] = fdec(pmax[i]);
}

// ---------------------------------------------------------------------------
// BN finalize
// ---------------------------------------------------------------------------
__global__ void finalize_kernel(const float* __restrict__ g,
                                const float* __restrict__ beta, int layer) {
    int i = threadIdx.x;
    float *s, *q, *a, *c; int n;
    if (layer == 1)      { s = g_s1; q = g_q1; a = g_a1; c = g_c1; n = 64;  }
    else if (layer == 2) { s = g_s2; q = g_q2; a = g_a2; c = g_c2; n = 64;  }
    else                 { s = g_s3; q = g_q3; a = g_a3; c = g_c3; n = 128; }
    if (i < n) {
        const float invN = 1.0f / (float)RR;
        float mean = s[i] * invN;
        float var  = fmaxf(q[i] * invN - mean*mean, 0.f);
        float inv  = rsqrtf(var + BN_EPS);
        float aa   = g[i] * inv;
        a[i] = aa;
        c[i] = beta[i] - mean * aa;
    }
}

// ---------------------------------------------------------------------------
// BN3 + ReLU on pooled maxima + transpose to (B, 128, M)
// ---------------------------------------------------------------------------
__global__ __launch_bounds__(256) void out3_kernel(float* __restrict__ out) {
    __shared__ float t[32][129];
    __shared__ float a3s[128], c3s[128];
    int tid = threadIdx.x;
    int b  = blockIdx.x >> 6;
    int m0 = (blockIdx.x & 63) << 5;
    if (tid < 128) { a3s[tid] = g_a3[tid]; c3s[tid] = g_c3[tid]; }
    __syncthreads();
    for (int i = tid; i < 32*128; i += 256) {
        int ml = i >> 7, c = i & 127;
        float v = g_pool[(size_t)((b*MM + m0 + ml) << 7) + c];
        t[ml][c] = fmaxf(fmaf(a3s[c], v, c3s[c]), 0.f);
    }
    __syncthreads();
    for (int i = tid; i < 32*128; i += 256) {
        int c = i >> 5, j = i & 31;
        out[(b*128 + c)*MM + m0 + j] = t[j][c];
    }
}

// ---------------------------------------------------------------------------
// launcher
// ---------------------------------------------------------------------------
extern "C" void kernel_launch(void* const* d_in, const int* in_sizes, int n_in,
                              void* d_out, int out_size) {
    const float* xyz   = (const float*)d_in[0];
    const float* feats = (const float*)d_in[1];
    const float* w1    = (const float*)d_in[2];
    const float* b1    = (const float*)d_in[3];
    const float* g1    = (const float*)d_in[4];
    const float* be1   = (const float*)d_in[5];
    const float* w2    = (const float*)d_in[6];
    const float* b2    = (const float*)d_in[7];
    const float* g2    = (const float*)d_in[8];
    const float* be2   = (const float*)d_in[9];
    const float* w3    = (const float*)d_in[10];
    const float* b3    = (const float*)d_in[11];
    const float* g3    = (const float*)d_in[12];
    const float* be3   = (const float*)d_in[13];

    float* out_centers = (float*)d_out;                 // (B, M, 3)
    float* out_feat    = out_centers + BB*MM*3;         // (B, 128, M)

    init_stats_kernel<<<1, 128>>>();
    prep_w_kernel<<<16, 256>>>(w1, w2, w3);

    dim3 tb(32, 8), tg(PP/32, CC/32, BB);
    transpose_kernel<<<tg, tb>>>(feats);

    knn_kernel<<<BB*MM/8, 256>>>(xyz, out_centers);

    mlp1_kernel<<<RR/128, 256>>>(xyz, w1, b1);
    finalize_kernel<<<1, 128>>>(g1, be1, 1);

    mlp23_kernel<2><<<RR/128, 256>>>(b2);
    finalize_kernel<<<1, 128>>>(g2, be2, 2);

    mlp23_kernel<3><<<RR/128, 256>>>(b3);
    finalize_kernel<<<1, 128>>>(g3, be3, 3);

    out3_kernel<<<BB*MM/32, 256>>>(out_feat);
}